// round 5
// baseline (speedup 1.0000x reference)
#include <cuda_runtime.h>

// UnPatcher: 2-level inverse Haar DWT, fully fused, float4-vectorized.
// in : [8, 256, 96, 96]  f32   (channels = 16 out-ch x 4 (level2 m) x 4 (level1 n))
// out: [8, 16, 384, 384] f32
//
// out[b,c, 4i + 2*p1 + p, 4j + 2*q1 + q] =
//   sum_{m,n} in[b, c + 16m + 64n, i, j] * (-1)^{(m&1)p + (m>>1)q + (n&1)p1 + (n>>1)q1}
// (rescaled Haar gain is exactly 1 per level, so all coefficients are +/-1)
//
// Each thread processes 4 consecutive input columns (one float4 per channel):
// 16 x LDG.128 in, 16 x STG.128 out (4 patch rows x 16 output columns).

#define BATCH  8
#define CO     16
#define HI     96
#define WI     96
#define CHS    (CO * HI * WI)            // f32 stride between the 16 channel groups
#define CHS4   (CHS / 4)                 // in float4 units
#define WI4    (WI / 4)                  // 24 float4 columns per input row
#define TOTAL4 (BATCH * CO * HI * WI4)   // 294912 threads

__device__ __forceinline__ float4 f4add(float4 a, float4 b) {
    return make_float4(a.x + b.x, a.y + b.y, a.z + b.z, a.w + b.w);
}
__device__ __forceinline__ float4 f4sub(float4 a, float4 b) {
    return make_float4(a.x - b.x, a.y - b.y, a.z - b.z, a.w - b.w);
}
__device__ __forceinline__ float f4get(const float4& v, int l) {
    return l == 0 ? v.x : l == 1 ? v.y : l == 2 ? v.z : v.w;
}

__global__ void __launch_bounds__(256)
unpatcher_fused_v4_kernel(const float* __restrict__ in, float* __restrict__ out)
{
    int t = blockIdx.x * 256 + threadIdx.x;
    if (t >= TOTAL4) return;

    int j4  = t % WI4;
    int tmp = t / WI4;
    int i   = tmp % HI;
    int bc  = tmp / HI;        // b*16 + c
    int b   = bc >> 4;
    int c   = bc & 15;

    // float4 base: in[b, c, i, 4*j4]
    const float4* __restrict__ base = (const float4*)(
        in + (((size_t)(b * 256 + c)) * HI + i) * WI) + j4;

    // 16 vector loads: v[4n + m] = in[b, c + 16m + 64n, i, 4j4..4j4+3]
    float4 v[16];
#pragma unroll
    for (int k = 0; k < 16; k++)
        v[k] = __ldcs(base + (size_t)k * CHS4);

    // Stage 1: height butterfly. For each width-coeff combo wi = 2*nw + mw,
    // produce 4 patch rows r = 2*p1 + p (componentwise over the 4 j-columns).
    float4 h[4][4];
#pragma unroll
    for (int nw = 0; nw < 2; nw++) {
#pragma unroll
        for (int mw = 0; mw < 2; mw++) {
            float4 c00 = v[8 * nw + 2 * mw + 0];  // nh=0, mh=0
            float4 c01 = v[8 * nw + 2 * mw + 1];  // nh=0, mh=1
            float4 c10 = v[8 * nw + 2 * mw + 4];  // nh=1, mh=0
            float4 c11 = v[8 * nw + 2 * mw + 5];  // nh=1, mh=1
            float4 u0 = f4add(c00, c01), u1 = f4sub(c00, c01);  // level-2 height bit
            float4 w0 = f4add(c10, c11), w1 = f4sub(c10, c11);
            int wi_ = 2 * nw + mw;
            h[wi_][0] = f4add(u0, w0);   // p=0, p1=0
            h[wi_][1] = f4add(u1, w1);   // p=1, p1=0
            h[wi_][2] = f4sub(u0, w0);   // p=0, p1=1
            h[wi_][3] = f4sub(u1, w1);   // p=1, p1=1
        }
    }

    // Stage 2: width butterfly + stores. Patch row r of input column j = 4*j4+l
    // produces output float4 at columns 4j..4j+3. Per r: 4 consecutive STG.128
    // (256 B contiguous per thread, fully coalesced across the warp).
    float4* obase = (float4*)(out + ((size_t)bc * (4 * HI) + 4 * i) * (4 * WI)) + 4 * j4;
    const int orow_stride = WI;  // output row = 384 floats = 96 float4s

#pragma unroll
    for (int r = 0; r < 4; r++) {
        float4* orow = obase + r * orow_stride;
#pragma unroll
        for (int l = 0; l < 4; l++) {
            float d00 = f4get(h[0][r], l);  // nw=0, mw=0
            float d01 = f4get(h[1][r], l);  // nw=0, mw=1
            float d10 = f4get(h[2][r], l);  // nw=1, mw=0
            float d11 = f4get(h[3][r], l);  // nw=1, mw=1
            float a0 = d00 + d01, a1 = d00 - d01;   // level-2 width bit
            float b0 = d10 + d11, b1 = d10 - d11;
            float4 o;
            o.x = a0 + b0;   // q=0, q1=0
            o.y = a1 + b1;   // q=1, q1=0
            o.z = a0 - b0;   // q=0, q1=1
            o.w = a1 - b1;   // q=1, q1=1
            __stcs(orow + l, o);
        }
    }
}

extern "C" void kernel_launch(void* const* d_in, const int* in_sizes, int n_in,
                              void* d_out, int out_size)
{
    const float* x = (const float*)d_in[0];
    float* y       = (float*)d_out;
    (void)in_sizes; (void)n_in; (void)out_size;

    int blocks = (TOTAL4 + 255) / 256;   // 1152 blocks of 256 threads
    unpatcher_fused_v4_kernel<<<blocks, 256>>>(x, y);
}

// round 6
// speedup vs baseline: 1.1352x; 1.1352x over previous
#include <cuda_runtime.h>

// UnPatcher: 2-level inverse Haar DWT, fully fused.
// in : [8, 256, 96, 96]  f32   (channels = 16 out-ch x 4 (level2 m) x 4 (level1 n))
// out: [8, 16, 384, 384] f32
//
// out[b,c, 4i + 2*p1 + p, 4j + 2*q1 + q] =
//   sum_{m,n} in[b, c + 16m + 64n, i, j] * (-1)^{(m&1)p + (m>>1)q + (n&1)p1 + (n>>1)q1}
// (rescaled Haar gain is exactly 1 per level -> all coefficients are +/-1)
//
// R3 geometry (scalar loads, one output float4 per patch row, lanes consecutive
// in j so every LDG.32 is 1 line/warp and every STG.128 is 4 lines/warp),
// but each thread handles TWO sites (rows i and i+48) for 2x memory-level
// parallelism: 32 loads in flight per thread.

#define BATCH  8
#define CO     16
#define HI     96
#define WI     96
#define CHS    (CO * HI * WI)                 // f32 stride between channel groups
#define HHALF  (HI / 2)                       // 48
#define TOTAL2 (BATCH * CO * HHALF * WI)      // 589824 threads (2 sites each)

__device__ __forceinline__ void butterfly_store(const float v[16], float4* obase)
{
    // Stage 1: height butterfly -> h[width-combo][patch row]
    float h[4][4];
#pragma unroll
    for (int nw = 0; nw < 2; nw++) {
#pragma unroll
        for (int mw = 0; mw < 2; mw++) {
            float c00 = v[8 * nw + 2 * mw + 0];  // nh=0, mh=0
            float c01 = v[8 * nw + 2 * mw + 1];  // nh=0, mh=1
            float c10 = v[8 * nw + 2 * mw + 4];  // nh=1, mh=0
            float c11 = v[8 * nw + 2 * mw + 5];  // nh=1, mh=1
            float u0 = c00 + c01, u1 = c00 - c01;   // level-2 height bit
            float w0 = c10 + c11, w1 = c10 - c11;
            int wi_ = 2 * nw + mw;
            h[wi_][0] = u0 + w0;   // p=0, p1=0
            h[wi_][1] = u1 + w1;   // p=1, p1=0
            h[wi_][2] = u0 - w0;   // p=0, p1=1
            h[wi_][3] = u1 - w1;   // p=1, p1=1
        }
    }

    // Stage 2: width butterfly + one float4 store per patch row.
    // Adjacent lanes (consecutive j) write adjacent float4s -> fully coalesced.
#pragma unroll
    for (int r = 0; r < 4; r++) {
        float d00 = h[0][r], d01 = h[1][r], d10 = h[2][r], d11 = h[3][r];
        float a0 = d00 + d01, a1 = d00 - d01;   // level-2 width bit
        float b0 = d10 + d11, b1 = d10 - d11;
        float4 o;
        o.x = a0 + b0;   // q=0, q1=0
        o.y = a1 + b1;   // q=1, q1=0
        o.z = a0 - b0;   // q=0, q1=1
        o.w = a1 - b1;   // q=1, q1=1
        __stcs(obase + r * WI, o);   // output row = 384 f32 = 96 float4s
    }
}

__global__ void __launch_bounds__(256)
unpatcher_fused_x2_kernel(const float* __restrict__ in, float* __restrict__ out)
{
    int t = blockIdx.x * 256 + threadIdx.x;
    if (t >= TOTAL2) return;

    int j   = t % WI;
    int tmp = t / WI;
    int i   = tmp % HHALF;        // site0 row; site1 row = i + 48
    int bc  = tmp / HHALF;        // b*16 + c
    int b   = bc >> 4;
    int c   = bc & 15;

    const float* __restrict__ base =
        in + (((size_t)(b * 256 + c)) * HI + i) * WI + j;

    // Issue all 32 loads up front (2 sites x 16 channel groups), all 1-line/warp.
    float v0[16], v1[16];
#pragma unroll
    for (int k = 0; k < 16; k++) {
        v0[k] = __ldcs(base + (size_t)k * CHS);
        v1[k] = __ldcs(base + (size_t)k * CHS + HHALF * WI);
    }

    float4* obase0 = (float4*)(out + ((size_t)bc * (4 * HI) + 4 * i) * (4 * WI)) + j;
    float4* obase1 = obase0 + (size_t)(4 * HHALF) * WI;   // +192 output rows

    butterfly_store(v0, obase0);
    butterfly_store(v1, obase1);
}

extern "C" void kernel_launch(void* const* d_in, const int* in_sizes, int n_in,
                              void* d_out, int out_size)
{
    const float* x = (const float*)d_in[0];
    float* y       = (float*)d_out;
    (void)in_sizes; (void)n_in; (void)out_size;

    int blocks = (TOTAL2 + 255) / 256;   // 2304 blocks of 256 threads
    unpatcher_fused_x2_kernel<<<blocks, 256>>>(x, y);
}

// round 7
// speedup vs baseline: 1.1364x; 1.0010x over previous
#include <cuda_runtime.h>

// UnPatcher: 2-level inverse Haar DWT, fully fused.
// in : [8, 256, 96, 96]  f32   (channels = 16 out-ch x 4 (level2 m) x 4 (level1 n))
// out: [8, 16, 384, 384] f32
//
// out[b,c, 4i + 2*p1 + p, 4j + 2*q1 + q] =
//   sum_{m,n} in[b, c + 16m + 64n, i, j] * (-1)^{(m&1)p + (m>>1)q + (n&1)p1 + (n>>1)q1}
// (rescaled Haar gain is exactly 1 per level -> all coefficients are +/-1)
//
// Geometry identical to the best (R3) kernel: one thread per input site,
// 16 scalar coalesced loads (1 line/warp each), 4 float4 stores (4 lines/warp
// each). Single change: output stores use streaming hint (__stcs) so the
// write-once output is evict-first in L2, leaving capacity for the input
// tensor (reread every graph replay) to stay L2-resident.

#define BATCH  8
#define CO     16
#define HI     96
#define WI     96
#define CHS    (CO * HI * WI)          // element stride between the 16 channel groups
#define TOTAL  (BATCH * CO * HI * WI)  // one thread per input spatial site = 1179648

__global__ void __launch_bounds__(256)
unpatcher_fused_stcs_kernel(const float* __restrict__ in, float* __restrict__ out)
{
    int t = blockIdx.x * 256 + threadIdx.x;
    if (t >= TOTAL) return;

    int j   = t % WI;
    int tmp = t / WI;
    int i   = tmp % HI;
    int bc  = tmp / HI;        // b*16 + c
    int b   = bc >> 4;
    int c   = bc & 15;

    // 16 coalesced loads: v[4n + m] = in[b, c + 16m + 64n, i, j]
    const float* __restrict__ base =
        in + (((size_t)(b * 256 + c)) * HI + i) * WI + j;

    float v[16];
#pragma unroll
    for (int k = 0; k < 16; k++)
        v[k] = __ldg(base + (size_t)k * CHS);

    // Stage 1: height butterfly -> h[width-combo][patch row r = 2*p1 + p]
    float h[4][4];
#pragma unroll
    for (int nw = 0; nw < 2; nw++) {
#pragma unroll
        for (int mw = 0; mw < 2; mw++) {
            float c00 = v[8 * nw + 2 * mw + 0];  // nh=0, mh=0
            float c01 = v[8 * nw + 2 * mw + 1];  // nh=0, mh=1
            float c10 = v[8 * nw + 2 * mw + 4];  // nh=1, mh=0
            float c11 = v[8 * nw + 2 * mw + 5];  // nh=1, mh=1
            float u0 = c00 + c01, u1 = c00 - c01;   // level-2 height bit
            float w0 = c10 + c11, w1 = c10 - c11;
            int wi_ = 2 * nw + mw;
            h[wi_][0] = u0 + w0;   // p=0, p1=0
            h[wi_][1] = u1 + w1;   // p=1, p1=0
            h[wi_][2] = u0 - w0;   // p=0, p1=1
            h[wi_][3] = u1 - w1;   // p=1, p1=1
        }
    }

    // Stage 2: width butterfly + one streaming float4 store per patch row.
    // Adjacent lanes (consecutive j) write adjacent float4s -> fully coalesced.
    float4* obase = (float4*)(out + ((size_t)bc * (4 * HI) + 4 * i) * (4 * WI)) + j;

#pragma unroll
    for (int r = 0; r < 4; r++) {
        float d00 = h[0][r], d01 = h[1][r], d10 = h[2][r], d11 = h[3][r];
        float a0 = d00 + d01, a1 = d00 - d01;   // level-2 width bit
        float b0 = d10 + d11, b1 = d10 - d11;
        float4 o;
        o.x = a0 + b0;   // q=0, q1=0
        o.y = a1 + b1;   // q=1, q1=0
        o.z = a0 - b0;   // q=0, q1=1
        o.w = a1 - b1;   // q=1, q1=1
        __stcs(obase + r * WI, o);   // output row = 384 f32 = 96 float4s
    }
}

extern "C" void kernel_launch(void* const* d_in, const int* in_sizes, int n_in,
                              void* d_out, int out_size)
{
    const float* x = (const float*)d_in[0];
    float* y       = (float*)d_out;
    (void)in_sizes; (void)n_in; (void)out_size;

    int blocks = (TOTAL + 255) / 256;   // 4608 blocks of 256 threads
    unpatcher_fused_stcs_kernel<<<blocks, 256>>>(x, y);
}

// round 9
// speedup vs baseline: 1.3097x; 1.1525x over previous
#include <cuda_runtime.h>

// UnPatcher: 2-level inverse Haar DWT, fully fused.
// in : [8, 256, 96, 96]  f32   (channels = 16 out-ch x 4 (level2 m) x 4 (level1 n))
// out: [8, 16, 384, 384] f32
//
// out[b,c, 4i + 2*p1 + p, 4j + 2*q1 + q] =
//   sum_{m,n} in[b, c + 16m + 64n, i, j] * (-1)^{(m&1)p + (m>>1)q + (n&1)p1 + (n>>1)q1}
// (rescaled Haar gain is exactly 1 per level -> all coefficients are +/-1)
//
// Exact R3 geometry (best so far, 27.1us): one thread per input site, 16
// scalar coalesced loads (1 line/warp each), 4 default float4 stores
// (4 lines/warp each). Single change vs R3: input loads carry an L2
// evict_last cache-hint policy (createpolicy + ld.global.nc.L2::cache_hint,
// the form this ptxas accepts for scalar loads) so the constant 75.5 MB
// input stays L2-resident across graph replays. Stores stay DEFAULT —
// R6 proved streaming stores regress.

#define BATCH  8
#define CO     16
#define HI     96
#define WI     96
#define CHS    (CO * HI * WI)          // element stride between the 16 channel groups
#define TOTAL  (BATCH * CO * HI * WI)  // one thread per input spatial site = 1179648

__device__ __forceinline__ unsigned long long make_evict_last_policy()
{
    unsigned long long pol;
    asm("createpolicy.fractional.L2::evict_last.b64 %0, 1.0;" : "=l"(pol));
    return pol;
}

__device__ __forceinline__ float ldg_hint(const float* p, unsigned long long pol)
{
    float v;
    asm("ld.global.nc.L2::cache_hint.f32 %0, [%1], %2;"
        : "=f"(v) : "l"(p), "l"(pol));
    return v;
}

__global__ void __launch_bounds__(256)
unpatcher_fused_hint_kernel(const float* __restrict__ in, float* __restrict__ out)
{
    int t = blockIdx.x * 256 + threadIdx.x;   // grid covers TOTAL exactly

    int j   = t % WI;
    int tmp = t / WI;
    int i   = tmp % HI;
    int bc  = tmp / HI;        // b*16 + c
    int b   = bc >> 4;
    int c   = bc & 15;

    const unsigned long long pol = make_evict_last_policy();

    // 16 coalesced loads: v[4n + m] = in[b, c + 16m + 64n, i, j]
    const float* __restrict__ base =
        in + (((size_t)(b * 256 + c)) * HI + i) * WI + j;

    float v[16];
#pragma unroll
    for (int k = 0; k < 16; k++)
        v[k] = ldg_hint(base + (size_t)k * CHS, pol);

    // Stage 1: height butterfly -> h[width-combo][patch row r = 2*p1 + p]
    float h[4][4];
#pragma unroll
    for (int nw = 0; nw < 2; nw++) {
#pragma unroll
        for (int mw = 0; mw < 2; mw++) {
            float c00 = v[8 * nw + 2 * mw + 0];  // nh=0, mh=0
            float c01 = v[8 * nw + 2 * mw + 1];  // nh=0, mh=1
            float c10 = v[8 * nw + 2 * mw + 4];  // nh=1, mh=0
            float c11 = v[8 * nw + 2 * mw + 5];  // nh=1, mh=1
            float u0 = c00 + c01, u1 = c00 - c01;   // level-2 height bit
            float w0 = c10 + c11, w1 = c10 - c11;
            int wi_ = 2 * nw + mw;
            h[wi_][0] = u0 + w0;   // p=0, p1=0
            h[wi_][1] = u1 + w1;   // p=1, p1=0
            h[wi_][2] = u0 - w0;   // p=0, p1=1
            h[wi_][3] = u1 - w1;   // p=1, p1=1
        }
    }

    // Stage 2: width butterfly + one DEFAULT float4 store per patch row.
    // Adjacent lanes (consecutive j) write adjacent float4s -> fully coalesced.
    float4* obase = (float4*)(out + ((size_t)bc * (4 * HI) + 4 * i) * (4 * WI)) + j;

#pragma unroll
    for (int r = 0; r < 4; r++) {
        float d00 = h[0][r], d01 = h[1][r], d10 = h[2][r], d11 = h[3][r];
        float a0 = d00 + d01, a1 = d00 - d01;   // level-2 width bit
        float b0 = d10 + d11, b1 = d10 - d11;
        float4 o;
        o.x = a0 + b0;   // q=0, q1=0
        o.y = a1 + b1;   // q=1, q1=0
        o.z = a0 - b0;   // q=0, q1=1
        o.w = a1 - b1;   // q=1, q1=1
        obase[r * WI] = o;   // output row = 384 f32 = 96 float4s
    }
}

extern "C" void kernel_launch(void* const* d_in, const int* in_sizes, int n_in,
                              void* d_out, int out_size)
{
    const float* x = (const float*)d_in[0];
    float* y       = (float*)d_out;
    (void)in_sizes; (void)n_in; (void)out_size;

    unpatcher_fused_hint_kernel<<<TOTAL / 256, 256>>>(x, y);   // 4608 blocks
}